// round 13
// baseline (speedup 1.0000x reference)
#include <cuda_runtime.h>
#include <cuda_fp16.h>
#include <cstdint>

#define Bv 512
#define Tv 256
#define Cv 384
#define Hv 64
#define N3 192
#define SCALE 0.125f

// ---------------------------------------------------------------------------
// Scratch (static __device__ globals; no cudaMalloc allowed)
// ---------------------------------------------------------------------------
__device__ __align__(16) __half g_Qh[(size_t)Bv * Tv * Hv];  // Q fp16 hi
__device__ __align__(16) __half g_Ql[(size_t)Bv * Tv * Hv];  // Q fp16 lo
__device__ __align__(16) __half g_K [(size_t)Bv * Tv * Hv];  // K fp16
__device__ __align__(16) __half g_V [(size_t)Bv * Tv * Hv];  // V fp16 (row-major)
__device__ float g_bcat[N3];
__device__ __align__(16) __half g_Bh[N3 * Cv];               // W^T fp16 [192][384]

// ---------------------------------------------------------------------------
// PTX helpers (sm_80-level only — assemble on compute_103)
// ---------------------------------------------------------------------------
__device__ __forceinline__ uint32_t smem_u32(const void* p) {
    uint32_t a;
    asm("{ .reg .u64 t; cvta.to.shared.u64 t, %1; cvt.u32.u64 %0, t; }"
        : "=r"(a) : "l"(p));
    return a;
}

__device__ __forceinline__ void ldsm4(uint32_t* r, uint32_t addr) {
    asm volatile("ldmatrix.sync.aligned.m8n8.x4.shared.b16 {%0,%1,%2,%3}, [%4];"
                 : "=r"(r[0]), "=r"(r[1]), "=r"(r[2]), "=r"(r[3]) : "r"(addr));
}
__device__ __forceinline__ void ldsm4t(uint32_t* r, uint32_t addr) {
    asm volatile("ldmatrix.sync.aligned.m8n8.x4.trans.shared.b16 {%0,%1,%2,%3}, [%4];"
                 : "=r"(r[0]), "=r"(r[1]), "=r"(r[2]), "=r"(r[3]) : "r"(addr));
}

__device__ __forceinline__ void mma_f16(float* d, const uint32_t* a,
                                        uint32_t b0, uint32_t b1) {
    asm volatile(
        "mma.sync.aligned.m16n8k16.row.col.f32.f16.f16.f32 "
        "{%0,%1,%2,%3}, {%4,%5,%6,%7}, {%8,%9}, {%0,%1,%2,%3};"
        : "+f"(d[0]), "+f"(d[1]), "+f"(d[2]), "+f"(d[3])
        : "r"(a[0]), "r"(a[1]), "r"(a[2]), "r"(a[3]), "r"(b0), "r"(b1));
}

__device__ __forceinline__ uint32_t pack_h2(float a, float b) {
    __half2 h = __floats2half2_rn(a, b);
    return *reinterpret_cast<uint32_t*>(&h);
}
__device__ __forceinline__ float h2_lo(uint32_t h) {
    return __half2float(__low2half(*reinterpret_cast<__half2*>(&h)));
}
__device__ __forceinline__ float h2_hi(uint32_t h) {
    return __half2float(__high2half(*reinterpret_cast<__half2*>(&h)));
}

// ---------------------------------------------------------------------------
// Pack W^T into fp16 [192][384] + bias vector
// ---------------------------------------------------------------------------
__global__ void pack_w_kernel(const float* __restrict__ Wq, const float* __restrict__ bq,
                              const float* __restrict__ Wk, const float* __restrict__ bk,
                              const float* __restrict__ Wv, const float* __restrict__ bv) {
    int i = blockIdx.x * blockDim.x + threadIdx.x;
    if (i < N3 * Cv) {
        int n = i / Cv, k = i % Cv;
        float w;
        if (n < 64)       w = Wq[k * Hv + n];
        else if (n < 128) w = Wk[k * Hv + n - 64];
        else              w = Wv[k * Hv + n - 128];
        g_Bh[i] = __float2half_rn(w);
    }
    if (i < N3) {
        g_bcat[i] = (i < 64) ? bq[i] : (i < 128 ? bk[i - 64] : bv[i - 128]);
    }
}

// ---------------------------------------------------------------------------
// QKV projection on HMMA: single-term fp16 (x_hi * W), fp32 accum.
// Both x AND B tiles register-prefetched one chunk ahead; chunk start is
// pure STS (no LDG->STS dependent stall in the serialized phase).
// SMEM: A[0,16K) B[16K,40K)
// ---------------------------------------------------------------------------
#define SM_B    16384
#define SMEM_GEMM 40960

__global__ __launch_bounds__(256, 1) void qkv_mma_kernel(const float* __restrict__ x) {
    extern __shared__ char smem[];
    const uint32_t sb = smem_u32(smem);
    const int tid  = threadIdx.x;
    const int lane = tid & 31;
    const int w    = tid >> 5;
    const int wm   = w & 3;
    const int wn   = w >> 2;
    const int row0 = blockIdx.x * 128;

    float acc[2][12][4];
#pragma unroll
    for (int mt = 0; mt < 2; ++mt)
#pragma unroll
        for (int j = 0; j < 12; ++j)
#pragma unroll
            for (int e = 0; e < 4; ++e) acc[mt][j][e] = 0.f;

    // Per-thread prefetch state: x (8 float4) and B (6 uint4)
    float4 xc[8], xn[8];
    uint4  bc[6], bn[6];
    // B indices are chunk-invariant per thread
    int bn_[6], bcc_[6];
#pragma unroll
    for (int i = 0; i < 6; ++i) {
        int idx = tid + i * 256;      // 0..1535
        bn_[i]  = idx >> 3;
        bcc_[i] = idx & 7;
    }
#pragma unroll
    for (int i = 0; i < 8; ++i) {
        int idx = tid + i * 256;
        int row = idx >> 4, g = idx & 15;
        xc[i] = *(const float4*)(x + (size_t)(row0 + row) * Cv + g * 4);
    }
#pragma unroll
    for (int i = 0; i < 6; ++i)
        bc[i] = *(const uint4*)((const char*)g_Bh + bn_[i] * 768 + bcc_[i] * 16);

    for (int c = 0; c < 6; ++c) {
        // ---- B tile: STS from prefetched registers, swizzled ----
#pragma unroll
        for (int i = 0; i < 6; ++i) {
            uint32_t dst = bn_[i] * 128 + ((bcc_[i] ^ (bn_[i] & 7)) * 16);
            *(uint4*)(smem + SM_B + dst) = bc[i];
        }
        // ---- A tile: prefetched registers -> fp16, swizzled ----
#pragma unroll
        for (int i = 0; i < 8; ++i) {
            int idx = tid + i * 256;
            int row = idx >> 4, g = idx & 15;
            float4 v = xc[i];
            uint32_t h01 = pack_h2(v.x, v.y);
            uint32_t h23 = pack_h2(v.z, v.w);
            uint32_t dst = row * 128 + (((g >> 1) ^ (row & 7)) * 16) + (g & 1) * 8;
            *(uint2*)(smem + dst) = make_uint2(h01, h23);
        }
        __syncthreads();

        // ---- prefetch next chunk (x and B) into registers ----
        if (c < 5) {
#pragma unroll
            for (int i = 0; i < 8; ++i) {
                int idx = tid + i * 256;
                int row = idx >> 4, g = idx & 15;
                xn[i] = *(const float4*)(x + (size_t)(row0 + row) * Cv +
                                         (c + 1) * 64 + g * 4);
            }
            const char* bb = (const char*)g_Bh + (c + 1) * 128;
#pragma unroll
            for (int i = 0; i < 6; ++i)
                bn[i] = *(const uint4*)(bb + bn_[i] * 768 + bcc_[i] * 16);
        }

        // ---- compute: 4 k-steps of 16 ----
#pragma unroll
        for (int ks = 0; ks < 4; ++ks) {
            const int chunk = ks * 2 + (lane >> 4);
            uint32_t ah[2][4];
#pragma unroll
            for (int mt = 0; mt < 2; ++mt) {
                int r = wm * 32 + mt * 16 + (lane & 15);
                uint32_t addr = sb + r * 128 + ((chunk ^ (r & 7)) * 16);
                ldsm4(ah[mt], addr);
            }
#pragma unroll
            for (int nt = 0; nt < 6; ++nt) {
                int n = wn * 96 + nt * 16 + (lane & 15);
                uint32_t baddr = sb + SM_B + n * 128 + ((chunk ^ (n & 7)) * 16);
                uint32_t bh[4];
                ldsm4(bh, baddr);
#pragma unroll
                for (int mt = 0; mt < 2; ++mt) {
                    mma_f16(acc[mt][2 * nt],     ah[mt], bh[0], bh[2]);
                    mma_f16(acc[mt][2 * nt + 1], ah[mt], bh[1], bh[3]);
                }
            }
        }
        __syncthreads();

#pragma unroll
        for (int i = 0; i < 8; ++i) xc[i] = xn[i];
#pragma unroll
        for (int i = 0; i < 6; ++i) bc[i] = bn[i];
    }

    // ---- epilogue: bias + fp16 stores (Q split hi/lo; K,V single) ----
#pragma unroll
    for (int mt = 0; mt < 2; ++mt) {
        int row = row0 + wm * 32 + mt * 16 + (lane >> 2);
#pragma unroll
        for (int j = 0; j < 12; ++j) {
            int col = wn * 96 + j * 8 + (lane & 3) * 2;
            float b0 = g_bcat[col], b1 = g_bcat[col + 1];
            float v0 = acc[mt][j][0] + b0, v1 = acc[mt][j][1] + b1;  // row
            float v2 = acc[mt][j][2] + b0, v3 = acc[mt][j][3] + b1;  // row+8
            if (col < 64) {
                size_t o0 = (size_t)row * Hv + col;
                size_t o1 = (size_t)(row + 8) * Hv + col;
                uint32_t h0 = pack_h2(v0, v1), h1 = pack_h2(v2, v3);
                *(uint32_t*)(g_Qh + o0) = h0;
                *(uint32_t*)(g_Qh + o1) = h1;
                *(uint32_t*)(g_Ql + o0) = pack_h2(v0 - h2_lo(h0), v1 - h2_hi(h0));
                *(uint32_t*)(g_Ql + o1) = pack_h2(v2 - h2_lo(h1), v3 - h2_hi(h1));
            } else if (col < 128) {
                size_t o0 = (size_t)row * Hv + col - 64;
                *(uint32_t*)(g_K + o0)                  = pack_h2(v0, v1);
                *(uint32_t*)(g_K + o0 + (size_t)8 * Hv) = pack_h2(v2, v3);
            } else {
                size_t o0 = (size_t)row * Hv + col - 128;
                *(uint32_t*)(g_V + o0)                  = pack_h2(v0, v1);
                *(uint32_t*)(g_V + o0 + (size_t)8 * Hv) = pack_h2(v2, v3);
            }
        }
    }
}

// ---------------------------------------------------------------------------
// HMMA flash-style causal attention, 2 CTAs per batch, 128 threads each.
// Q/Q_lo fragments loaded DIRECTLY from global in mma A-fragment layout
// (no Q smem): row = r0+mt*16+(lane>>2)(+8), col = ks*16+(lane&3)*2(+8).
// SMEM: K[0,32K) V[32K,64K) -> 64KB, 2 CTAs/SM by regs.
// Row-range split: half 0 -> {0,7,1,6}, half 1 -> {2,5,3,4} (18 tiles each).
// ---------------------------------------------------------------------------
#define AT_K  0
#define AT_V  32768
#define SMEM_ATTN 65536

__global__ __launch_bounds__(128, 2) void attn_mma_kernel(float* __restrict__ out) {
    extern __shared__ char smem[];
    const uint32_t sb = smem_u32(smem);
    const int cta  = blockIdx.x;
    const int b    = cta >> 1;
    const int half = cta & 1;
    const int tid  = threadIdx.x;
    const int lane = tid & 31;
    const int w    = tid >> 5;            // 0..3
    const int base = w >> 1;
    const int rw   = (half == 0) ? ((w & 1) ? 7 - base : base)
                                 : ((w & 1) ? 5 - base : 2 + base);
    const int r0   = rw * 32;

    const __half* Qhb = g_Qh + (size_t)b * Tv * Hv;
    const __half* Qlb = g_Ql + (size_t)b * Tv * Hv;
    const __half* Kb  = g_K  + (size_t)b * Tv * Hv;
    const __half* Vb  = g_V  + (size_t)b * Tv * Hv;

    // ---- stage K,V: swizzled uint4 copies (128B rows) ----
    for (int i = tid; i < 2048; i += 128) {
        int r = i >> 3, cc = i & 7;
        uint32_t dst = r * 128 + ((cc ^ (r & 7)) * 16);
        const size_t src = (size_t)r * Hv + cc * 8;
        *(uint4*)(smem + AT_K + dst) = *(const uint4*)(Kb + src);
        *(uint4*)(smem + AT_V + dst) = *(const uint4*)(Vb + src);
    }

    // ---- Q fragments direct from global (loop-invariant, A-fragment layout) ----
    uint32_t qh[4][2][4], ql[4][2][4];
#pragma unroll
    for (int ks = 0; ks < 4; ++ks)
#pragma unroll
        for (int mt = 0; mt < 2; ++mt) {
            int row = r0 + mt * 16 + (lane >> 2);
            int col = ks * 16 + (lane & 3) * 2;
            size_t o = (size_t)row * Hv + col;
            qh[ks][mt][0] = *(const uint32_t*)(Qhb + o);
            qh[ks][mt][1] = *(const uint32_t*)(Qhb + o + (size_t)8 * Hv);
            qh[ks][mt][2] = *(const uint32_t*)(Qhb + o + 8);
            qh[ks][mt][3] = *(const uint32_t*)(Qhb + o + (size_t)8 * Hv + 8);
            ql[ks][mt][0] = *(const uint32_t*)(Qlb + o);
            ql[ks][mt][1] = *(const uint32_t*)(Qlb + o + (size_t)8 * Hv);
            ql[ks][mt][2] = *(const uint32_t*)(Qlb + o + 8);
            ql[ks][mt][3] = *(const uint32_t*)(Qlb + o + (size_t)8 * Hv + 8);
        }
    __syncthreads();

    // ---- accumulators ----
    float o[2][8][4];
#pragma unroll
    for (int mt = 0; mt < 2; ++mt)
#pragma unroll
        for (int j = 0; j < 8; ++j)
#pragma unroll
            for (int e = 0; e < 4; ++e) o[mt][j][e] = 0.f;
    float lsum[2][2] = {{0.f, 0.f}, {0.f, 0.f}};

    // ---- kv tiles: jt = 0..rw, tile jt==rw is the masked diagonal ----
    for (int jt = 0; jt <= rw; ++jt) {
        const int kv0 = jt * 32;
        float sacc[2][4][4];
#pragma unroll
        for (int mt = 0; mt < 2; ++mt)
#pragma unroll
            for (int j = 0; j < 4; ++j)
#pragma unroll
                for (int e = 0; e < 4; ++e) sacc[mt][j][e] = 0.f;

        // S = Q K^T (2-term: qh + ql, K single)
#pragma unroll
        for (int ks = 0; ks < 4; ++ks) {
#pragma unroll
            for (int nt = 0; nt < 2; ++nt) {
                const int chunk = ks * 2 + (lane >> 4);
                int n = kv0 + nt * 16 + (lane & 15);
                uint32_t baddr = sb + AT_K + n * 128 + ((chunk ^ (n & 7)) * 16);
                uint32_t kh[4];
                ldsm4(kh, baddr);
#pragma unroll
                for (int mt = 0; mt < 2; ++mt) {
                    mma_f16(sacc[mt][2 * nt],     qh[ks][mt], kh[0], kh[2]);
                    mma_f16(sacc[mt][2 * nt + 1], qh[ks][mt], kh[1], kh[3]);
                    mma_f16(sacc[mt][2 * nt],     ql[ks][mt], kh[0], kh[2]);
                    mma_f16(sacc[mt][2 * nt + 1], ql[ks][mt], kh[1], kh[3]);
                }
            }
        }

        // softmax numerators (+ causal mask on diagonal tile), l accumulation
        const bool diag = (jt == rw);
#pragma unroll
        for (int mt = 0; mt < 2; ++mt)
#pragma unroll
            for (int nt2 = 0; nt2 < 4; ++nt2)
#pragma unroll
                for (int e = 0; e < 4; ++e) {
                    float s = sacc[mt][nt2][e] * SCALE;
                    float p = __expf(s);
                    if (diag) {
                        int jloc = nt2 * 8 + (lane & 3) * 2 + (e & 1);
                        int iloc = mt * 16 + (lane >> 2) + ((e >= 2) ? 8 : 0);
                        if (jloc > iloc) p = 0.f;
                    }
                    lsum[mt][e >> 1] += p;
                    sacc[mt][nt2][e] = p;
                }

        // repack P (C-layout) into A-fragments, single fp16
        uint32_t ph[2][2][4];
#pragma unroll
        for (int mt = 0; mt < 2; ++mt)
#pragma unroll
            for (int ks2 = 0; ks2 < 2; ++ks2) {
                const float* c0 = sacc[mt][2 * ks2];
                const float* c1 = sacc[mt][2 * ks2 + 1];
                ph[mt][ks2][0] = pack_h2(c0[0], c0[1]);
                ph[mt][ks2][1] = pack_h2(c0[2], c0[3]);
                ph[mt][ks2][2] = pack_h2(c1[0], c1[1]);
                ph[mt][ks2][3] = pack_h2(c1[2], c1[3]);
            }

        // O += P V (single-term) via ldmatrix.trans on row-major V
#pragma unroll
        for (int ks2 = 0; ks2 < 2; ++ks2) {
            int vr = kv0 + ks2 * 16 + (lane & 7) + ((lane >> 4) << 3);
#pragma unroll
            for (int nth = 0; nth < 4; ++nth) {
                int ccol = nth * 2 + ((lane >> 3) & 1);
                uint32_t vaddr = sb + AT_V + vr * 128 + ((ccol ^ (vr & 7)) * 16);
                uint32_t vh[4];
                ldsm4t(vh, vaddr);
#pragma unroll
                for (int mt = 0; mt < 2; ++mt) {
                    mma_f16(o[mt][2 * nth],     ph[mt][ks2], vh[0], vh[2]);
                    mma_f16(o[mt][2 * nth + 1], ph[mt][ks2], vh[1], vh[3]);
                }
            }
        }
    }

    // ---- reduce l across the 4 lanes sharing each row, normalize, store ----
#pragma unroll
    for (int mt = 0; mt < 2; ++mt)
#pragma unroll
        for (int hh = 0; hh < 2; ++hh) {
            float v = lsum[mt][hh];
            v += __shfl_xor_sync(0xFFFFFFFF, v, 1);
            v += __shfl_xor_sync(0xFFFFFFFF, v, 2);
            lsum[mt][hh] = 1.0f / v;
        }

#pragma unroll
    for (int mt = 0; mt < 2; ++mt) {
        int row = r0 + mt * 16 + (lane >> 2);
#pragma unroll
        for (int j = 0; j < 8; ++j) {
            int col = j * 8 + (lane & 3) * 2;
            float2 v0 = make_float2(o[mt][j][0] * lsum[mt][0],
                                    o[mt][j][1] * lsum[mt][0]);
            float2 v1 = make_float2(o[mt][j][2] * lsum[mt][1],
                                    o[mt][j][3] * lsum[mt][1]);
            *(float2*)(out + ((size_t)(b * Tv + row)) * Hv + col)     = v0;
            *(float2*)(out + ((size_t)(b * Tv + row + 8)) * Hv + col) = v1;
        }
    }
}

// ---------------------------------------------------------------------------
extern "C" void kernel_launch(void* const* d_in, const int* in_sizes, int n_in,
                              void* d_out, int out_size) {
    const float* x  = (const float*)d_in[0];
    const float* Wq = (const float*)d_in[1];
    const float* bq = (const float*)d_in[2];
    const float* Wk = (const float*)d_in[3];
    const float* bk = (const float*)d_in[4];
    const float* Wv = (const float*)d_in[5];
    const float* bv = (const float*)d_in[6];
    float* out = (float*)d_out;

    pack_w_kernel<<<(N3 * Cv + 255) / 256, 256>>>(Wq, bq, Wk, bk, Wv, bv);

    cudaFuncSetAttribute(qkv_mma_kernel, cudaFuncAttributeMaxDynamicSharedMemorySize,
                         SMEM_GEMM);
    qkv_mma_kernel<<<(Bv * Tv) / 128, 256, SMEM_GEMM>>>(x);

    cudaFuncSetAttribute(attn_mma_kernel, cudaFuncAttributeMaxDynamicSharedMemorySize,
                         SMEM_ATTN);
    attn_mma_kernel<<<2 * Bv, 128, SMEM_ATTN>>>(out);
}

// round 16
// speedup vs baseline: 1.0923x; 1.0923x over previous
#include <cuda_runtime.h>
#include <cuda_fp16.h>
#include <cstdint>

#define Bv 512
#define Tv 256
#define Cv 384
#define Hv 64
#define N3 192
#define SCALE 0.125f

// ---------------------------------------------------------------------------
// Scratch (static __device__ globals; no cudaMalloc allowed)
// ---------------------------------------------------------------------------
__device__ float g_bcat[N3];
__device__ __align__(16) __half g_Bh[N3 * Cv];   // W^T fp16 [192][384] k-contig

// ---------------------------------------------------------------------------
// PTX helpers (sm_80-level only — assemble on compute_103)
// ---------------------------------------------------------------------------
__device__ __forceinline__ uint32_t smem_u32(const void* p) {
    uint32_t a;
    asm("{ .reg .u64 t; cvta.to.shared.u64 t, %1; cvt.u32.u64 %0, t; }"
        : "=r"(a) : "l"(p));
    return a;
}

__device__ __forceinline__ void ldsm4(uint32_t* r, uint32_t addr) {
    asm volatile("ldmatrix.sync.aligned.m8n8.x4.shared.b16 {%0,%1,%2,%3}, [%4];"
                 : "=r"(r[0]), "=r"(r[1]), "=r"(r[2]), "=r"(r[3]) : "r"(addr));
}
__device__ __forceinline__ void ldsm4t(uint32_t* r, uint32_t addr) {
    asm volatile("ldmatrix.sync.aligned.m8n8.x4.trans.shared.b16 {%0,%1,%2,%3}, [%4];"
                 : "=r"(r[0]), "=r"(r[1]), "=r"(r[2]), "=r"(r[3]) : "r"(addr));
}

__device__ __forceinline__ void mma_f16(float* d, const uint32_t* a,
                                        uint32_t b0, uint32_t b1) {
    asm volatile(
        "mma.sync.aligned.m16n8k16.row.col.f32.f16.f16.f32 "
        "{%0,%1,%2,%3}, {%4,%5,%6,%7}, {%8,%9}, {%0,%1,%2,%3};"
        : "+f"(d[0]), "+f"(d[1]), "+f"(d[2]), "+f"(d[3])
        : "r"(a[0]), "r"(a[1]), "r"(a[2]), "r"(a[3]), "r"(b0), "r"(b1));
}

__device__ __forceinline__ uint32_t pack_h2(float a, float b) {
    __half2 h = __floats2half2_rn(a, b);
    return *reinterpret_cast<uint32_t*>(&h);
}
__device__ __forceinline__ float h2_lo(uint32_t h) {
    return __half2float(__low2half(*reinterpret_cast<__half2*>(&h)));
}
__device__ __forceinline__ float h2_hi(uint32_t h) {
    return __half2float(__high2half(*reinterpret_cast<__half2*>(&h)));
}

// ---------------------------------------------------------------------------
// Pack W^T into fp16 [192][384] + bias vector
// ---------------------------------------------------------------------------
__global__ void pack_w_kernel(const float* __restrict__ Wq, const float* __restrict__ bq,
                              const float* __restrict__ Wk, const float* __restrict__ bk,
                              const float* __restrict__ Wv, const float* __restrict__ bv) {
    int i = blockIdx.x * blockDim.x + threadIdx.x;
    if (i < N3 * Cv) {
        int n = i / Cv, k = i % Cv;
        float w;
        if (n < 64)       w = Wq[k * Hv + n];
        else if (n < 128) w = Wk[k * Hv + n - 64];
        else              w = Wv[k * Hv + n - 128];
        g_Bh[i] = __float2half_rn(w);
    }
    if (i < N3) {
        g_bcat[i] = (i < 64) ? bq[i] : (i < 128 ? bk[i - 64] : bv[i - 128]);
    }
}

// ---------------------------------------------------------------------------
// FUSED kernel: one CTA per batch (256 threads).
//  Phase 1 (x2 passes of 128 rows): round-12 projection body, epilogue writes
//  Q_hi/Q_lo/K/V directly into swizzled SMEM (same image staging built before).
//  Phase 2: round-12 attention body with the staging loop deleted.
// SMEM: Qh[0,32K) Ql[32K,64K) K[64K,96K) V[96K,128K) A[128K,144K) B[144K,168K)
//  -> 172032 bytes total (B tile spans 192*128 = 24576 ending exactly at 168K).
// ---------------------------------------------------------------------------
#define FS_QH 0
#define FS_QL 32768
#define FS_K  65536
#define FS_V  98304
#define FS_A  131072
#define FS_B  147456
#define SMEM_FUSED 172032

__global__ __launch_bounds__(256, 1) void fused_attn_kernel(
    const float* __restrict__ x, float* __restrict__ out) {
    extern __shared__ char smem[];
    const uint32_t sb = smem_u32(smem);
    const int b    = blockIdx.x;
    const int tid  = threadIdx.x;
    const int lane = tid & 31;
    const int w    = tid >> 5;
    const int wm   = w & 3;          // projection M warp
    const int wn   = w >> 2;         // projection N warp

    // =====================================================================
    // Phase 1: QKV projection, two M=128 passes, outputs to SMEM
    // =====================================================================
    for (int pass = 0; pass < 2; ++pass) {
        const int row0 = b * Tv + pass * 128;   // global x row base

        float acc[2][12][4];
#pragma unroll
        for (int mt = 0; mt < 2; ++mt)
#pragma unroll
            for (int j = 0; j < 12; ++j)
#pragma unroll
                for (int e = 0; e < 4; ++e) acc[mt][j][e] = 0.f;

        float4 xc[8], xn[8];
#pragma unroll
        for (int i = 0; i < 8; ++i) {
            int idx = tid + i * 256;
            int row = idx >> 4, g = idx & 15;
            xc[i] = *(const float4*)(x + (size_t)(row0 + row) * Cv + g * 4);
        }

        for (int c = 0; c < 6; ++c) {
            // ---- B tile: [192 n][64 k] fp16, uint4 copies, swizzled ----
            {
                const char* bh = (const char*)g_Bh + c * 128;   // row stride 768B
#pragma unroll
                for (int i = tid; i < 1536; i += 256) {
                    int n = i >> 3, cc = i & 7;
                    uint32_t dst = n * 128 + ((cc ^ (n & 7)) * 16);
                    *(uint4*)(smem + FS_B + dst) =
                        *(const uint4*)(bh + n * 768 + cc * 16);
                }
            }
            // ---- A tile: prefetched registers -> fp16, swizzled ----
#pragma unroll
            for (int i = 0; i < 8; ++i) {
                int idx = tid + i * 256;
                int row = idx >> 4, g = idx & 15;
                float4 v = xc[i];
                uint32_t h01 = pack_h2(v.x, v.y);
                uint32_t h23 = pack_h2(v.z, v.w);
                uint32_t dst = FS_A + row * 128 +
                               (((g >> 1) ^ (row & 7)) * 16) + (g & 1) * 8;
                *(uint2*)(smem + dst) = make_uint2(h01, h23);
            }
            __syncthreads();

            // ---- prefetch next x chunk into registers (covered by compute) ----
            if (c < 5) {
#pragma unroll
                for (int i = 0; i < 8; ++i) {
                    int idx = tid + i * 256;
                    int row = idx >> 4, g = idx & 15;
                    xn[i] = *(const float4*)(x + (size_t)(row0 + row) * Cv +
                                             (c + 1) * 64 + g * 4);
                }
            }

            // ---- compute: 4 k-steps of 16 ----
#pragma unroll
            for (int ks = 0; ks < 4; ++ks) {
                const int chunk = ks * 2 + (lane >> 4);
                uint32_t ah[2][4];
#pragma unroll
                for (int mt = 0; mt < 2; ++mt) {
                    int r = wm * 32 + mt * 16 + (lane & 15);
                    uint32_t addr = sb + FS_A + r * 128 + ((chunk ^ (r & 7)) * 16);
                    ldsm4(ah[mt], addr);
                }
#pragma unroll
                for (int nt = 0; nt < 6; ++nt) {
                    int n = wn * 96 + nt * 16 + (lane & 15);
                    uint32_t baddr = sb + FS_B + n * 128 + ((chunk ^ (n & 7)) * 16);
                    uint32_t bh[4];
                    ldsm4(bh, baddr);
#pragma unroll
                    for (int mt = 0; mt < 2; ++mt) {
                        mma_f16(acc[mt][2 * nt],     ah[mt], bh[0], bh[2]);
                        mma_f16(acc[mt][2 * nt + 1], ah[mt], bh[1], bh[3]);
                    }
                }
            }
            __syncthreads();

#pragma unroll
            for (int i = 0; i < 8; ++i) xc[i] = xn[i];
        }

        // ---- epilogue: bias + fp16 writes into swizzled SMEM images ----
#pragma unroll
        for (int mt = 0; mt < 2; ++mt) {
            int lr = pass * 128 + wm * 32 + mt * 16 + (lane >> 2);  // local row
#pragma unroll
            for (int j = 0; j < 12; ++j) {
                int col = wn * 96 + j * 8 + (lane & 3) * 2;
                float b0 = g_bcat[col], b1 = g_bcat[col + 1];
                float v0 = acc[mt][j][0] + b0, v1 = acc[mt][j][1] + b1;  // lr
                float v2 = acc[mt][j][2] + b0, v3 = acc[mt][j][3] + b1;  // lr+8
                uint32_t base;
                int hc;                       // head-dim column 0..63
                if (col < 64)       { base = FS_QH; hc = col; }
                else if (col < 128) { base = FS_K;  hc = col - 64; }
                else                { base = FS_V;  hc = col - 128; }
                int cc = hc >> 3, byo = (hc & 7) * 2;
                uint32_t a0 = base + lr * 128 + ((cc ^ (lr & 7)) * 16) + byo;
                uint32_t a1 = base + (lr + 8) * 128 + ((cc ^ ((lr + 8) & 7)) * 16) + byo;
                uint32_t h0 = pack_h2(v0, v1), h1 = pack_h2(v2, v3);
                *(uint32_t*)(smem + a0) = h0;
                *(uint32_t*)(smem + a1) = h1;
                if (col < 64) {  // Q also gets lo residual image
                    *(uint32_t*)(smem + a0 + (FS_QL - FS_QH)) =
                        pack_h2(v0 - h2_lo(h0), v1 - h2_hi(h0));
                    *(uint32_t*)(smem + a1 + (FS_QL - FS_QH)) =
                        pack_h2(v2 - h2_lo(h1), v3 - h2_hi(h1));
                }
            }
        }
        __syncthreads();   // epilogue writes visible before next pass / attention
    }

    // =====================================================================
    // Phase 2: causal attention (round-12 body, staging deleted)
    // =====================================================================
    const int rw = (w < 4) ? w : 11 - w;     // balanced row-range id
    const int r0 = rw * 32;

    // ---- hoist Q fragments (loop-invariant per warp) ----
    uint32_t qh[4][2][4], ql[4][2][4];
#pragma unroll
    for (int ks = 0; ks < 4; ++ks) {
        const int chunk = ks * 2 + (lane >> 4);
#pragma unroll
        for (int mt = 0; mt < 2; ++mt) {
            int r = r0 + mt * 16 + (lane & 15);
            uint32_t addr = sb + FS_QH + r * 128 + ((chunk ^ (r & 7)) * 16);
            ldsm4(qh[ks][mt], addr);
            ldsm4(ql[ks][mt], addr + (FS_QL - FS_QH));
        }
    }

    // ---- accumulators ----
    float o[2][8][4];
#pragma unroll
    for (int mt = 0; mt < 2; ++mt)
#pragma unroll
        for (int j = 0; j < 8; ++j)
#pragma unroll
            for (int e = 0; e < 4; ++e) o[mt][j][e] = 0.f;
    float lsum[2][2] = {{0.f, 0.f}, {0.f, 0.f}};

    // ---- kv tiles: jt = 0..rw, tile jt==rw is the masked diagonal ----
    for (int jt = 0; jt <= rw; ++jt) {
        const int kv0 = jt * 32;
        float sacc[2][4][4];
#pragma unroll
        for (int mt = 0; mt < 2; ++mt)
#pragma unroll
            for (int j = 0; j < 4; ++j)
#pragma unroll
                for (int e = 0; e < 4; ++e) sacc[mt][j][e] = 0.f;

        // S = Q K^T (2-term: qh + ql, K single)
#pragma unroll
        for (int ks = 0; ks < 4; ++ks) {
#pragma unroll
            for (int nt = 0; nt < 2; ++nt) {
                const int chunk = ks * 2 + (lane >> 4);
                int n = kv0 + nt * 16 + (lane & 15);
                uint32_t baddr = sb + FS_K + n * 128 + ((chunk ^ (n & 7)) * 16);
                uint32_t kh[4];
                ldsm4(kh, baddr);
#pragma unroll
                for (int mt = 0; mt < 2; ++mt) {
                    mma_f16(sacc[mt][2 * nt],     qh[ks][mt], kh[0], kh[2]);
                    mma_f16(sacc[mt][2 * nt + 1], qh[ks][mt], kh[1], kh[3]);
                    mma_f16(sacc[mt][2 * nt],     ql[ks][mt], kh[0], kh[2]);
                    mma_f16(sacc[mt][2 * nt + 1], ql[ks][mt], kh[1], kh[3]);
                }
            }
        }

        // softmax numerators (+ causal mask on diagonal tile), l accumulation
        const bool diag = (jt == rw);
#pragma unroll
        for (int mt = 0; mt < 2; ++mt)
#pragma unroll
            for (int nt2 = 0; nt2 < 4; ++nt2)
#pragma unroll
                for (int e = 0; e < 4; ++e) {
                    float s = sacc[mt][nt2][e] * SCALE;
                    float p = __expf(s);
                    if (diag) {
                        int jloc = nt2 * 8 + (lane & 3) * 2 + (e & 1);
                        int iloc = mt * 16 + (lane >> 2) + ((e >= 2) ? 8 : 0);
                        if (jloc > iloc) p = 0.f;
                    }
                    lsum[mt][e >> 1] += p;
                    sacc[mt][nt2][e] = p;
                }

        // repack P (C-layout) into A-fragments, single fp16
        uint32_t ph[2][2][4];
#pragma unroll
        for (int mt = 0; mt < 2; ++mt)
#pragma unroll
            for (int ks2 = 0; ks2 < 2; ++ks2) {
                const float* c0 = sacc[mt][2 * ks2];
                const float* c1 = sacc[mt][2 * ks2 + 1];
                ph[mt][ks2][0] = pack_h2(c0[0], c0[1]);
                ph[mt][ks2][1] = pack_h2(c0[2], c0[3]);
                ph[mt][ks2][2] = pack_h2(c1[0], c1[1]);
                ph[mt][ks2][3] = pack_h2(c1[2], c1[3]);
            }

        // O += P V (single-term) via ldmatrix.trans on row-major V
#pragma unroll
        for (int ks2 = 0; ks2 < 2; ++ks2) {
            int vr = kv0 + ks2 * 16 + (lane & 7) + ((lane >> 4) << 3);
#pragma unroll
            for (int nth = 0; nth < 4; ++nth) {
                int ccol = nth * 2 + ((lane >> 3) & 1);
                uint32_t vaddr = sb + FS_V + vr * 128 + ((ccol ^ (vr & 7)) * 16);
                uint32_t vh[4];
                ldsm4t(vh, vaddr);
#pragma unroll
                for (int mt = 0; mt < 2; ++mt) {
                    mma_f16(o[mt][2 * nth],     ph[mt][ks2], vh[0], vh[2]);
                    mma_f16(o[mt][2 * nth + 1], ph[mt][ks2], vh[1], vh[3]);
                }
            }
        }
    }

    // ---- reduce l across the 4 lanes sharing each row, normalize, store ----
#pragma unroll
    for (int mt = 0; mt < 2; ++mt)
#pragma unroll
        for (int hh = 0; hh < 2; ++hh) {
            float v = lsum[mt][hh];
            v += __shfl_xor_sync(0xFFFFFFFF, v, 1);
            v += __shfl_xor_sync(0xFFFFFFFF, v, 2);
            lsum[mt][hh] = 1.0f / v;
        }

#pragma unroll
    for (int mt = 0; mt < 2; ++mt) {
        int row = r0 + mt * 16 + (lane >> 2);
#pragma unroll
        for (int j = 0; j < 8; ++j) {
            int col = j * 8 + (lane & 3) * 2;
            float2 v0 = make_float2(o[mt][j][0] * lsum[mt][0],
                                    o[mt][j][1] * lsum[mt][0]);
            float2 v1 = make_float2(o[mt][j][2] * lsum[mt][1],
                                    o[mt][j][3] * lsum[mt][1]);
            *(float2*)(out + ((size_t)(b * Tv + row)) * Hv + col)     = v0;
            *(float2*)(out + ((size_t)(b * Tv + row + 8)) * Hv + col) = v1;
        }
    }
}

// ---------------------------------------------------------------------------
extern "C" void kernel_launch(void* const* d_in, const int* in_sizes, int n_in,
                              void* d_out, int out_size) {
    const float* x  = (const float*)d_in[0];
    const float* Wq = (const float*)d_in[1];
    const float* bq = (const float*)d_in[2];
    const float* Wk = (const float*)d_in[3];
    const float* bk = (const float*)d_in[4];
    const float* Wv = (const float*)d_in[5];
    const float* bv = (const float*)d_in[6];
    float* out = (float*)d_out;

    pack_w_kernel<<<(N3 * Cv + 255) / 256, 256>>>(Wq, bq, Wk, bk, Wv, bv);

    cudaFuncSetAttribute(fused_attn_kernel,
                         cudaFuncAttributeMaxDynamicSharedMemorySize, SMEM_FUSED);
    fused_attn_kernel<<<Bv, 256, SMEM_FUSED>>>(x, out);
}

// round 17
// speedup vs baseline: 1.3257x; 1.2137x over previous
#include <cuda_runtime.h>
#include <cuda_fp16.h>
#include <cstdint>

#define Bv 512
#define Tv 256
#define Cv 384
#define Hv 64
#define N3 192
#define SCALE 0.125f

// ---------------------------------------------------------------------------
// Scratch (static __device__ globals; no cudaMalloc allowed)
// ---------------------------------------------------------------------------
__device__ float g_bcat[N3];
__device__ __align__(16) __half g_Bh[N3 * Cv];   // W^T fp16 [192][384] k-contig

// ---------------------------------------------------------------------------
// PTX helpers (sm_80-level only — assemble on compute_103)
// ---------------------------------------------------------------------------
__device__ __forceinline__ uint32_t smem_u32(const void* p) {
    uint32_t a;
    asm("{ .reg .u64 t; cvta.to.shared.u64 t, %1; cvt.u32.u64 %0, t; }"
        : "=r"(a) : "l"(p));
    return a;
}

__device__ __forceinline__ void ldsm4(uint32_t* r, uint32_t addr) {
    asm volatile("ldmatrix.sync.aligned.m8n8.x4.shared.b16 {%0,%1,%2,%3}, [%4];"
                 : "=r"(r[0]), "=r"(r[1]), "=r"(r[2]), "=r"(r[3]) : "r"(addr));
}
__device__ __forceinline__ void ldsm4t(uint32_t* r, uint32_t addr) {
    asm volatile("ldmatrix.sync.aligned.m8n8.x4.trans.shared.b16 {%0,%1,%2,%3}, [%4];"
                 : "=r"(r[0]), "=r"(r[1]), "=r"(r[2]), "=r"(r[3]) : "r"(addr));
}

__device__ __forceinline__ void mma_f16(float* d, const uint32_t* a,
                                        uint32_t b0, uint32_t b1) {
    asm volatile(
        "mma.sync.aligned.m16n8k16.row.col.f32.f16.f16.f32 "
        "{%0,%1,%2,%3}, {%4,%5,%6,%7}, {%8,%9}, {%0,%1,%2,%3};"
        : "+f"(d[0]), "+f"(d[1]), "+f"(d[2]), "+f"(d[3])
        : "r"(a[0]), "r"(a[1]), "r"(a[2]), "r"(a[3]), "r"(b0), "r"(b1));
}

__device__ __forceinline__ uint32_t pack_h2(float a, float b) {
    __half2 h = __floats2half2_rn(a, b);
    return *reinterpret_cast<uint32_t*>(&h);
}
__device__ __forceinline__ float h2_lo(uint32_t h) {
    return __half2float(__low2half(*reinterpret_cast<__half2*>(&h)));
}
__device__ __forceinline__ float h2_hi(uint32_t h) {
    return __half2float(__high2half(*reinterpret_cast<__half2*>(&h)));
}

// ---------------------------------------------------------------------------
// Pack W^T into fp16 [192][384] + bias vector
// ---------------------------------------------------------------------------
__global__ void pack_w_kernel(const float* __restrict__ Wq, const float* __restrict__ bq,
                              const float* __restrict__ Wk, const float* __restrict__ bk,
                              const float* __restrict__ Wv, const float* __restrict__ bv) {
    int i = blockIdx.x * blockDim.x + threadIdx.x;
    if (i < N3 * Cv) {
        int n = i / Cv, k = i % Cv;
        float w;
        if (n < 64)       w = Wq[k * Hv + n];
        else if (n < 128) w = Wk[k * Hv + n - 64];
        else              w = Wv[k * Hv + n - 128];
        g_Bh[i] = __float2half_rn(w);
    }
    if (i < N3) {
        g_bcat[i] = (i < 64) ? bq[i] : (i < 128 ? bk[i - 64] : bv[i - 128]);
    }
}

// ---------------------------------------------------------------------------
// FUSED kernel: one CTA per batch (256 threads).
//  Phase 1 (x2 passes of 128 rows): projection, epilogue writes Q_hi/Q_lo/K/V
//  directly into swizzled SMEM images. x prefetch reuses xc in place (xc is
//  dead after the A-tile conversion, before the barrier) — no xn array.
//  Phase 2: attention on the resident SMEM images.
// SMEM: Qh[0,32K) Ql[32K,64K) K[64K,96K) V[96K,128K) A[128K,144K) B[144K,168K)
// ---------------------------------------------------------------------------
#define FS_QH 0
#define FS_QL 32768
#define FS_K  65536
#define FS_V  98304
#define FS_A  131072
#define FS_B  147456
#define SMEM_FUSED 172032

__global__ __launch_bounds__(256, 1) void fused_attn_kernel(
    const float* __restrict__ x, float* __restrict__ out) {
    extern __shared__ char smem[];
    const uint32_t sb = smem_u32(smem);
    const int b    = blockIdx.x;
    const int tid  = threadIdx.x;
    const int lane = tid & 31;
    const int w    = tid >> 5;
    const int wm   = w & 3;          // projection M warp
    const int wn   = w >> 2;         // projection N warp

    // =====================================================================
    // Phase 1: QKV projection, two M=128 passes, outputs to SMEM
    // =====================================================================
    for (int pass = 0; pass < 2; ++pass) {
        const int row0 = b * Tv + pass * 128;   // global x row base

        float acc[2][12][4];
#pragma unroll
        for (int mt = 0; mt < 2; ++mt)
#pragma unroll
            for (int j = 0; j < 12; ++j)
#pragma unroll
                for (int e = 0; e < 4; ++e) acc[mt][j][e] = 0.f;

        float4 xc[8];
#pragma unroll
        for (int i = 0; i < 8; ++i) {
            int idx = tid + i * 256;
            int row = idx >> 4, g = idx & 15;
            xc[i] = *(const float4*)(x + (size_t)(row0 + row) * Cv + g * 4);
        }

        for (int c = 0; c < 6; ++c) {
            // ---- B tile: [192 n][64 k] fp16, uint4 copies, swizzled ----
            {
                const char* bh = (const char*)g_Bh + c * 128;   // row stride 768B
#pragma unroll
                for (int i = tid; i < 1536; i += 256) {
                    int n = i >> 3, cc = i & 7;
                    uint32_t dst = n * 128 + ((cc ^ (n & 7)) * 16);
                    *(uint4*)(smem + FS_B + dst) =
                        *(const uint4*)(bh + n * 768 + cc * 16);
                }
            }
            // ---- A tile: xc registers -> fp16, swizzled (xc dead after) ----
#pragma unroll
            for (int i = 0; i < 8; ++i) {
                int idx = tid + i * 256;
                int row = idx >> 4, g = idx & 15;
                float4 v = xc[i];
                uint32_t h01 = pack_h2(v.x, v.y);
                uint32_t h23 = pack_h2(v.z, v.w);
                uint32_t dst = FS_A + row * 128 +
                               (((g >> 1) ^ (row & 7)) * 16) + (g & 1) * 8;
                *(uint2*)(smem + dst) = make_uint2(h01, h23);
            }
            __syncthreads();

            // ---- prefetch next x chunk IN PLACE into xc (covered by compute) ----
            if (c < 5) {
#pragma unroll
                for (int i = 0; i < 8; ++i) {
                    int idx = tid + i * 256;
                    int row = idx >> 4, g = idx & 15;
                    xc[i] = *(const float4*)(x + (size_t)(row0 + row) * Cv +
                                             (c + 1) * 64 + g * 4);
                }
            }

            // ---- compute: 4 k-steps of 16 ----
#pragma unroll
            for (int ks = 0; ks < 4; ++ks) {
                const int chunk = ks * 2 + (lane >> 4);
                uint32_t ah[2][4];
#pragma unroll
                for (int mt = 0; mt < 2; ++mt) {
                    int r = wm * 32 + mt * 16 + (lane & 15);
                    uint32_t addr = sb + FS_A + r * 128 + ((chunk ^ (r & 7)) * 16);
                    ldsm4(ah[mt], addr);
                }
#pragma unroll
                for (int nt = 0; nt < 6; ++nt) {
                    int n = wn * 96 + nt * 16 + (lane & 15);
                    uint32_t baddr = sb + FS_B + n * 128 + ((chunk ^ (n & 7)) * 16);
                    uint32_t bh[4];
                    ldsm4(bh, baddr);
#pragma unroll
                    for (int mt = 0; mt < 2; ++mt) {
                        mma_f16(acc[mt][2 * nt],     ah[mt], bh[0], bh[2]);
                        mma_f16(acc[mt][2 * nt + 1], ah[mt], bh[1], bh[3]);
                    }
                }
            }
            __syncthreads();
        }

        // ---- epilogue: bias + fp16 writes into swizzled SMEM images ----
#pragma unroll
        for (int mt = 0; mt < 2; ++mt) {
            int lr = pass * 128 + wm * 32 + mt * 16 + (lane >> 2);  // local row
#pragma unroll
            for (int j = 0; j < 12; ++j) {
                int col = wn * 96 + j * 8 + (lane & 3) * 2;
                float b0 = g_bcat[col], b1 = g_bcat[col + 1];
                float v0 = acc[mt][j][0] + b0, v1 = acc[mt][j][1] + b1;  // lr
                float v2 = acc[mt][j][2] + b0, v3 = acc[mt][j][3] + b1;  // lr+8
                uint32_t base;
                int hc;                       // head-dim column 0..63
                if (col < 64)       { base = FS_QH; hc = col; }
                else if (col < 128) { base = FS_K;  hc = col - 64; }
                else                { base = FS_V;  hc = col - 128; }
                int cc = hc >> 3, byo = (hc & 7) * 2;
                uint32_t a0 = base + lr * 128 + ((cc ^ (lr & 7)) * 16) + byo;
                uint32_t a1 = base + (lr + 8) * 128 + ((cc ^ ((lr + 8) & 7)) * 16) + byo;
                uint32_t h0 = pack_h2(v0, v1), h1 = pack_h2(v2, v3);
                *(uint32_t*)(smem + a0) = h0;
                *(uint32_t*)(smem + a1) = h1;
                if (col < 64) {  // Q also gets lo residual image
                    *(uint32_t*)(smem + a0 + (FS_QL - FS_QH)) =
                        pack_h2(v0 - h2_lo(h0), v1 - h2_hi(h0));
                    *(uint32_t*)(smem + a1 + (FS_QL - FS_QH)) =
                        pack_h2(v2 - h2_lo(h1), v3 - h2_hi(h1));
                }
            }
        }
        __syncthreads();   // epilogue writes visible before next pass / attention
    }

    // =====================================================================
    // Phase 2: causal attention on resident SMEM images
    // =====================================================================
    const int rw = (w < 4) ? w : 11 - w;     // balanced row-range id
    const int r0 = rw * 32;

    // ---- hoist Q fragments (loop-invariant per warp) ----
    uint32_t qh[4][2][4], ql[4][2][4];
#pragma unroll
    for (int ks = 0; ks < 4; ++ks) {
        const int chunk = ks * 2 + (lane >> 4);
#pragma unroll
        for (int mt = 0; mt < 2; ++mt) {
            int r = r0 + mt * 16 + (lane & 15);
            uint32_t addr = sb + FS_QH + r * 128 + ((chunk ^ (r & 7)) * 16);
            ldsm4(qh[ks][mt], addr);
            ldsm4(ql[ks][mt], addr + (FS_QL - FS_QH));
        }
    }

    // ---- accumulators ----
    float o[2][8][4];
#pragma unroll
    for (int mt = 0; mt < 2; ++mt)
#pragma unroll
        for (int j = 0; j < 8; ++j)
#pragma unroll
            for (int e = 0; e < 4; ++e) o[mt][j][e] = 0.f;
    float lsum[2][2] = {{0.f, 0.f}, {0.f, 0.f}};

    // ---- kv tiles: jt = 0..rw, tile jt==rw is the masked diagonal ----
    for (int jt = 0; jt <= rw; ++jt) {
        const int kv0 = jt * 32;
        float sacc[2][4][4];
#pragma unroll
        for (int mt = 0; mt < 2; ++mt)
#pragma unroll
            for (int j = 0; j < 4; ++j)
#pragma unroll
                for (int e = 0; e < 4; ++e) sacc[mt][j][e] = 0.f;

        // S = Q K^T (2-term: qh + ql, K single)
#pragma unroll
        for (int ks = 0; ks < 4; ++ks) {
#pragma unroll
            for (int nt = 0; nt < 2; ++nt) {
                const int chunk = ks * 2 + (lane >> 4);
                int n = kv0 + nt * 16 + (lane & 15);
                uint32_t baddr = sb + FS_K + n * 128 + ((chunk ^ (n & 7)) * 16);
                uint32_t kh[4];
                ldsm4(kh, baddr);
#pragma unroll
                for (int mt = 0; mt < 2; ++mt) {
                    mma_f16(sacc[mt][2 * nt],     qh[ks][mt], kh[0], kh[2]);
                    mma_f16(sacc[mt][2 * nt + 1], qh[ks][mt], kh[1], kh[3]);
                    mma_f16(sacc[mt][2 * nt],     ql[ks][mt], kh[0], kh[2]);
                    mma_f16(sacc[mt][2 * nt + 1], ql[ks][mt], kh[1], kh[3]);
                }
            }
        }

        // softmax numerators (+ causal mask on diagonal tile), l accumulation
        const bool diag = (jt == rw);
#pragma unroll
        for (int mt = 0; mt < 2; ++mt)
#pragma unroll
            for (int nt2 = 0; nt2 < 4; ++nt2)
#pragma unroll
                for (int e = 0; e < 4; ++e) {
                    float s = sacc[mt][nt2][e] * SCALE;
                    float p = __expf(s);
                    if (diag) {
                        int jloc = nt2 * 8 + (lane & 3) * 2 + (e & 1);
                        int iloc = mt * 16 + (lane >> 2) + ((e >= 2) ? 8 : 0);
                        if (jloc > iloc) p = 0.f;
                    }
                    lsum[mt][e >> 1] += p;
                    sacc[mt][nt2][e] = p;
                }

        // repack P (C-layout) into A-fragments, single fp16
        uint32_t ph[2][2][4];
#pragma unroll
        for (int mt = 0; mt < 2; ++mt)
#pragma unroll
            for (int ks2 = 0; ks2 < 2; ++ks2) {
                const float* c0 = sacc[mt][2 * ks2];
                const float* c1 = sacc[mt][2 * ks2 + 1];
                ph[mt][ks2][0] = pack_h2(c0[0], c0[1]);
                ph[mt][ks2][1] = pack_h2(c0[2], c0[3]);
                ph[mt][ks2][2] = pack_h2(c1[0], c1[1]);
                ph[mt][ks2][3] = pack_h2(c1[2], c1[3]);
            }

        // O += P V (single-term) via ldmatrix.trans on row-major V
#pragma unroll
        for (int ks2 = 0; ks2 < 2; ++ks2) {
            int vr = kv0 + ks2 * 16 + (lane & 7) + ((lane >> 4) << 3);
#pragma unroll
            for (int nth = 0; nth < 4; ++nth) {
                int ccol = nth * 2 + ((lane >> 3) & 1);
                uint32_t vaddr = sb + FS_V + vr * 128 + ((ccol ^ (vr & 7)) * 16);
                uint32_t vh[4];
                ldsm4t(vh, vaddr);
#pragma unroll
                for (int mt = 0; mt < 2; ++mt) {
                    mma_f16(o[mt][2 * nth],     ph[mt][ks2], vh[0], vh[2]);
                    mma_f16(o[mt][2 * nth + 1], ph[mt][ks2], vh[1], vh[3]);
                }
            }
        }
    }

    // ---- reduce l across the 4 lanes sharing each row, normalize, store ----
#pragma unroll
    for (int mt = 0; mt < 2; ++mt)
#pragma unroll
        for (int hh = 0; hh < 2; ++hh) {
            float v = lsum[mt][hh];
            v += __shfl_xor_sync(0xFFFFFFFF, v, 1);
            v += __shfl_xor_sync(0xFFFFFFFF, v, 2);
            lsum[mt][hh] = 1.0f / v;
        }

#pragma unroll
    for (int mt = 0; mt < 2; ++mt) {
        int row = r0 + mt * 16 + (lane >> 2);
#pragma unroll
        for (int j = 0; j < 8; ++j) {
            int col = j * 8 + (lane & 3) * 2;
            float2 v0 = make_float2(o[mt][j][0] * lsum[mt][0],
                                    o[mt][j][1] * lsum[mt][0]);
            float2 v1 = make_float2(o[mt][j][2] * lsum[mt][1],
                                    o[mt][j][3] * lsum[mt][1]);
            *(float2*)(out + ((size_t)(b * Tv + row)) * Hv + col)     = v0;
            *(float2*)(out + ((size_t)(b * Tv + row + 8)) * Hv + col) = v1;
        }
    }
}

// ---------------------------------------------------------------------------
extern "C" void kernel_launch(void* const* d_in, const int* in_sizes, int n_in,
                              void* d_out, int out_size) {
    const float* x  = (const float*)d_in[0];
    const float* Wq = (const float*)d_in[1];
    const float* bq = (const float*)d_in[2];
    const float* Wk = (const float*)d_in[3];
    const float* bk = (const float*)d_in[4];
    const float* Wv = (const float*)d_in[5];
    const float* bv = (const float*)d_in[6];
    float* out = (float*)d_out;

    pack_w_kernel<<<(N3 * Cv + 255) / 256, 256>>>(Wq, bq, Wk, bk, Wv, bv);

    cudaFuncSetAttribute(fused_attn_kernel,
                         cudaFuncAttributeMaxDynamicSharedMemorySize, SMEM_FUSED);
    fused_attn_kernel<<<Bv, 256, SMEM_FUSED>>>(x, out);
}